// round 13
// baseline (speedup 1.0000x reference)
#include <cuda_runtime.h>
#include <cstdint>

// Kalman predict: x_hat = Ap x ; P_hat = Ap P Ap^T + Q,  Ap = triu(relu(A))
// Best-known structure (R10): 1 thread per batch, per-warp smem staging,
// cp.async.cg overlap of the x/x_hat path with the P tile fill, __stcs
// streaming stores. R12: L2::256B prefetch on cp.async (longer same-direction
// DRAM bursts), BLOCK=128 (finer wave packing at the same 20-warp/SM reg
// ceiling), x load hoisted above the A loads.

#define BLOCK   128
#define WARPS   (BLOCK / 32)
#define BPW     32                 // batches per warp
#define STRIDE  68                 // padded floats per batch row (64 + 4)

__device__ __forceinline__ void cp_async16(unsigned int smem_addr, const void* gmem) {
    asm volatile("cp.async.cg.shared.global.L2::256B [%0], [%1], 16;"
                 :: "r"(smem_addr), "l"(gmem) : "memory");
}
__device__ __forceinline__ void cp_async_commit() {
    asm volatile("cp.async.commit_group;" ::: "memory");
}
__device__ __forceinline__ void cp_async_wait_all() {
    asm volatile("cp.async.wait_group 0;" ::: "memory");
}

__global__ void __launch_bounds__(BLOCK)
kf_predict_kernel(const float* __restrict__ x,
                  const float* __restrict__ P,
                  const float* __restrict__ A,
                  const float* __restrict__ sigma_p,
                  const float* __restrict__ sigma_v,
                  float* __restrict__ x_hat,
                  float* __restrict__ P_hat,
                  int B)
{
    __shared__ float sbuf[WARPS][BPW * STRIDE];   // 4 * 8704 B = 34816 B

    const int w = threadIdx.x >> 5;
    const int t = threadIdx.x & 31;
    const int warpBatch0 = (blockIdx.x * WARPS + w) * BPW;
    if (warpBatch0 >= B) return;                  // whole-warp uniform exit
    const int b = warpBatch0 + t;                 // this thread's batch
    const bool fullWarp = (warpBatch0 + BPW <= B);
    const bool valid = (b < B);

    float* sb = sbuf[w];

    // ---- kick off async staging of this warp's 32 batches of P ----
    {
        const float4* src = reinterpret_cast<const float4*>(P) + (size_t)warpBatch0 * 16;
        if (fullWarp) {
#pragma unroll
            for (int k = 0; k < 16; k++) {
                int g4 = t + 32 * k;
                int batch = g4 >> 4;
                int col   = (g4 & 15) << 2;
                unsigned int sa = (unsigned int)__cvta_generic_to_shared(&sb[batch * STRIDE + col]);
                cp_async16(sa, src + g4);
            }
        } else {
            const int lim4 = (B - warpBatch0) * 16; // valid float4s in this tile
#pragma unroll
            for (int k = 0; k < 16; k++) {
                int g4 = t + 32 * k;
                if (g4 < lim4) {
                    int batch = g4 >> 4;
                    int col   = (g4 & 15) << 2;
                    unsigned int sa = (unsigned int)__cvta_generic_to_shared(&sb[batch * STRIDE + col]);
                    cp_async16(sa, src + g4);
                }
            }
        }
        cp_async_commit();
    }

    // ---- x: issue early so its latency overlaps the A/ap construction ----
    float4 xa0, xa1;
    {
        const int xb = valid ? b : (B - 1);
        const float4* x4 = reinterpret_cast<const float4*>(x + (size_t)xb * 8);
        xa0 = __ldg(x4 + 0);
        xa1 = __ldg(x4 + 1);
    }

    // ---- Ap = triu(relu(A)) : 16 uniform float4 loads (L1-resident) ----
    float ap[8][8];
    {
        const float4* A4 = reinterpret_cast<const float4*>(A);
#pragma unroll
        for (int i = 0; i < 8; i++) {
            float4 lo = __ldg(A4 + i * 2);
            float4 hi = __ldg(A4 + i * 2 + 1);
            float row[8] = {lo.x, lo.y, lo.z, lo.w, hi.x, hi.y, hi.z, hi.w};
#pragma unroll
            for (int j = 0; j < 8; j++)
                ap[i][j] = (j >= i) ? fmaxf(row[j], 0.0f) : 0.0f;
        }
    }
    const float sp = __ldg(sigma_p);
    const float sv = __ldg(sigma_v);

    float xv[8];
    xv[0] = xa0.x; xv[1] = xa0.y; xv[2] = xa0.z; xv[3] = xa0.w;
    xv[4] = xa1.x; xv[5] = xa1.y; xv[6] = xa1.z; xv[7] = xa1.w;

    // ---- x_hat = Ap x (overlapping the async fill), streaming store ----
    if (valid) {
        float xh[8];
#pragma unroll
        for (int i = 0; i < 8; i++) {
            float s = 0.0f;
#pragma unroll
            for (int j = 0; j < 8; j++)
                if (j >= i) s = fmaf(ap[i][j], xv[j], s);
            xh[i] = s;
        }
        float4* o4 = reinterpret_cast<float4*>(x_hat + (size_t)b * 8);
        __stcs(o4 + 0, make_float4(xh[0], xh[1], xh[2], xh[3]));
        __stcs(o4 + 1, make_float4(xh[4], xh[5], xh[6], xh[7]));
    }

    // ---- wait for P tile, then read own batch row (conflict-free, STRIDE=68) ----
    cp_async_wait_all();
    __syncwarp();

    float p[8][8];
#pragma unroll
    for (int r = 0; r < 8; r++) {
        float4 lo = *reinterpret_cast<const float4*>(&sb[t * STRIDE + r * 8]);
        float4 hi = *reinterpret_cast<const float4*>(&sb[t * STRIDE + r * 8 + 4]);
        p[r][0] = lo.x; p[r][1] = lo.y; p[r][2] = lo.z; p[r][3] = lo.w;
        p[r][4] = hi.x; p[r][5] = hi.y; p[r][6] = hi.z; p[r][7] = hi.w;
    }

    // ---- stage 2 first (row-local): p[j] <- v_j, v_j[l] = sum_{k>=l} p[j][k]*ap[l][k] ----
#pragma unroll
    for (int j = 0; j < 8; j++) {
        float vrow[8];
#pragma unroll
        for (int l = 0; l < 8; l++) {
            float s = 0.0f;
#pragma unroll
            for (int k = 0; k < 8; k++)
                if (k >= l) s = fmaf(p[j][k], ap[l][k], s);
            vrow[l] = s;
        }
#pragma unroll
        for (int l = 0; l < 8; l++) p[j][l] = vrow[l];
    }

    // ---- Q diagonal terms ----
    const float h  = xv[2];
    const float wd = xv[3];
    float dq[8];
    dq[0] = h * sp;  dq[1] = wd * sp;  dq[2] = h * sp;  dq[3] = wd * sp;
    dq[4] = h * sv;  dq[5] = wd * sv;  dq[6] = h * sv;  dq[7] = wd * sv;

    // ---- stage 1: o[i][l] = sum_{j>=i} ap[i][j] * v_j[l] ; rows -> smem ----
#pragma unroll
    for (int i = 0; i < 8; i++) {
        float orow[8];
#pragma unroll
        for (int l = 0; l < 8; l++) {
            float s = 0.0f;
#pragma unroll
            for (int j = 0; j < 8; j++)
                if (j >= i) s = fmaf(ap[i][j], p[j][l], s);
            orow[l] = s;
        }
        orow[i] = fmaf(dq[i], dq[i], orow[i]);
        *reinterpret_cast<float4*>(&sb[t * STRIDE + i * 8]) =
            make_float4(orow[0], orow[1], orow[2], orow[3]);
        *reinterpret_cast<float4*>(&sb[t * STRIDE + i * 8 + 4]) =
            make_float4(orow[4], orow[5], orow[6], orow[7]);
    }
    __syncwarp();

    // ---- coalesced streaming store of the warp tile to P_hat ----
    {
        float4* dst = reinterpret_cast<float4*>(P_hat) + (size_t)warpBatch0 * 16;
        if (fullWarp) {
#pragma unroll
            for (int k = 0; k < 16; k++) {
                int g4 = t + 32 * k;
                int batch = g4 >> 4;
                int col   = (g4 & 15) << 2;
                __stcs(dst + g4, *reinterpret_cast<const float4*>(&sb[batch * STRIDE + col]));
            }
        } else {
            const int lim4 = (B - warpBatch0) * 16;
#pragma unroll
            for (int k = 0; k < 16; k++) {
                int g4 = t + 32 * k;
                if (g4 < lim4) {
                    int batch = g4 >> 4;
                    int col   = (g4 & 15) << 2;
                    __stcs(dst + g4, *reinterpret_cast<const float4*>(&sb[batch * STRIDE + col]));
                }
            }
        }
    }
}

extern "C" void kernel_launch(void* const* d_in, const int* in_sizes, int n_in,
                              void* d_out, int out_size)
{
    const float* x  = (const float*)d_in[0];   // (B, 8, 1)
    const float* P  = (const float*)d_in[1];   // (B, 8, 8)
    const float* A  = (const float*)d_in[2];   // (8, 8)
    const float* sp = (const float*)d_in[3];   // scalar
    const float* sv = (const float*)d_in[4];   // scalar

    const int B = in_sizes[0] / 8;

    float* out   = (float*)d_out;
    float* x_hat = out;                        // B*8 floats
    float* P_hat = out + (size_t)B * 8;        // B*64 floats

    const int batchesPerBlock = WARPS * BPW;   // 128
    const int blocks = (B + batchesPerBlock - 1) / batchesPerBlock;
    kf_predict_kernel<<<blocks, BLOCK>>>(x, P, A, sp, sv, x_hat, P_hat, B);
}